// round 17
// baseline (speedup 1.0000x reference)
#include <cuda_runtime.h>
#include <cuda_fp16.h>
#include <cstdint>

// Model_62886911148434 — seed-guided cluster loss.
// A: gather + mean-pool via cp.async rolling pipeline (8 stages, zero barriers
//    in the hot loop; RF-decoupled in-flight depth). 160 thr: lanes 0-74 own
//    the teacher table, 80-154 the student table.
// B: mma.sync GEMM with fp16 accumulators, 3-stage cp.async (R16 best)
// C: warp-per-sentence softmax/loss + fused deterministic reduction

#define B_ 2048
#define S_ 2048
#define L_ 64
#define LS_ 8
#define D_ 300
#define DP2 320          // padded K (zeros in 300..319): 5 chunks of 64 halfs
#define C_ 64
#define NCHUNK 5
#define LOSS_BLOCKS 256
#define GEMM_SMEM (96 * 1024)   // 3 stages x (A 16KB + B 16KB)
#define PIPE 8

__device__ __half g_snt[2][B_ * DP2];
__device__ __half g_sd [2][S_ * DP2];
__device__ float g_pmax[2][B_ * C_];
__device__ float g_lossb[B_];
__device__ unsigned int g_cnt;   // zero-initialized; reset by last block

__device__ __forceinline__ uint32_t smem_u32(const void* p) {
    uint32_t a;
    asm("{ .reg .u64 t; cvta.to.shared.u64 t, %1; cvt.u32.u64 %0, t; }"
        : "=r"(a) : "l"(p));
    return a;
}

#define CP_ASYNC16(dst, src) \
    asm volatile("cp.async.cg.shared.global [%0], [%1], 16;" \
                 :: "r"(dst), "l"(src) : "memory")
#define CP_COMMIT()  asm volatile("cp.async.commit_group;" ::: "memory")
#define CP_WAIT1()   asm volatile("cp.async.wait_group 1;" ::: "memory")
#define CP_WAIT_P()  asm volatile("cp.async.wait_group %0;" :: "n"(PIPE - 1) : "memory")
#define CP_WAIT0()   asm volatile("cp.async.wait_group 0;" ::: "memory")

// ---------------- Stage A: cp.async-pipelined gather + mean-pool -------------
// One block per row, 160 threads. Thread t: t<75 -> teacher chunk t;
// 80<=t<155 -> student chunk t-80; others pad. Each thread copies AND consumes
// the same 16B chunk -> per-thread wait_group is the only synchronization.
__global__ void __launch_bounds__(160) emb_kernel(
    const int* __restrict__ sents, const int* __restrict__ seeds,
    const float* __restrict__ mask,
    const float* __restrict__ embT, const float* __restrict__ embS)
{
    __shared__ int   s_tok[L_];
    __shared__ float s_msk[L_];
    __shared__ __align__(16) float4 stg[PIPE][152];   // [stage][75 T | pad | 75 S]

    const int t = threadIdx.x;
    const int row = blockIdx.x;
    const bool isT = (t < 80);
    const int f = isT ? t : (t - 80);          // chunk index 0..79
    const bool act = (f < 75);
    const int slot = isT ? f : (76 + f);
    const float* tab = isT ? embT : embS;
    const uint32_t sdst = smem_u32(&stg[0][slot]);   // stage 0 slot address
    // stage stride in bytes
    const uint32_t sstride = (uint32_t)(sizeof(float4) * 152);

    float4 a = make_float4(0.f, 0.f, 0.f, 0.f);
    float sc;
    __half* dst;

    if (row < B_) {
        if (t < L_) {
            s_tok[t] = sents[row * L_ + t];
            s_msk[t] = mask [row * L_ + t];
        }
        __syncthreads();

        // prologue: issue tokens 0..PIPE-1, one commit group each
        #pragma unroll
        for (int l = 0; l < PIPE; l++) {
            if (act)
                CP_ASYNC16(sdst + (uint32_t)l * sstride,
                           tab + (size_t)s_tok[l] * D_ + f * 4);
            CP_COMMIT();
        }

        for (int l = 0; l < L_; l++) {
            CP_WAIT_P();                       // token l's group complete
            if (act) {
                const float4 v = stg[l & (PIPE - 1)][slot];
                const float m = s_msk[l];
                a.x += v.x * m; a.y += v.y * m; a.z += v.z * m; a.w += v.w * m;
            }
            const int ln = l + PIPE;
            if (ln < L_ && act)
                CP_ASYNC16(sdst + (uint32_t)(ln & (PIPE - 1)) * sstride,
                           tab + (size_t)s_tok[ln] * D_ + f * 4);
            CP_COMMIT();                       // constant group cadence
        }

        float msum = 0.f;
        #pragma unroll
        for (int l = 0; l < L_; l++) msum += s_msk[l];
        sc = 1.f / fmaxf(msum, 1.f);
        dst = (isT ? &g_snt[0][0] : &g_snt[1][0]) + (size_t)row * DP2;
    } else {
        const int s = row - B_;
        if (t < LS_) s_tok[t] = seeds[s * LS_ + t];
        __syncthreads();

        // all 8 seed tokens in flight at once, then drain
        #pragma unroll
        for (int l = 0; l < LS_; l++) {
            if (act)
                CP_ASYNC16(sdst + (uint32_t)l * sstride,
                           tab + (size_t)s_tok[l] * D_ + f * 4);
        }
        CP_COMMIT();
        CP_WAIT0();
        if (act) {
            #pragma unroll
            for (int l = 0; l < LS_; l++) {
                const float4 v = stg[l][slot];
                a.x += v.x; a.y += v.y; a.z += v.z; a.w += v.w;
            }
        }
        sc = 1.f / (float)LS_;
        dst = (isT ? &g_sd[0][0] : &g_sd[1][0]) + (size_t)s * DP2;
    }

    if (act) {
        ((__half2*)(dst + f * 4))[0] = __floats2half2_rn(a.x * sc, a.y * sc);
        ((__half2*)(dst + f * 4))[1] = __floats2half2_rn(a.z * sc, a.w * sc);
    } else {
        // f in 75..79: zero pad dims 300..319 of this thread's table
        const __half2 z = __floats2half2_rn(0.f, 0.f);
        ((__half2*)(dst + f * 4))[0] = z;
        ((__half2*)(dst + f * 4))[1] = z;
    }
}

// ---------------- Stage B: fp16-acc mma.sync GEMM + per-cluster max ----------
// Block: 256 threads (8 warps, 2x4), tile 128(m) x 128(n), warp tile 64x32.
// 3-stage cp.async pipeline: wait_group 1 -> sync -> issue ch+2 -> compute ch.
__global__ void __launch_bounds__(256, 2) gemm_max_kernel()
{
    extern __shared__ __align__(16) uint4 smem_dyn[];

    const int tid = threadIdx.x;
    const int wid = tid >> 5, lane = tid & 31;
    const int warp_m = wid >> 2, warp_n = wid & 3;
    const int z = blockIdx.z, bcol = blockIdx.x, brow = blockIdx.y;

    const __half* Ag = &g_snt[z][(size_t)brow * 128 * DP2];
    const __half* Bg = &g_sd [z][(size_t)bcol * 128 * DP2];

    const uint32_t aBase = smem_u32(smem_dyn);
    const uint32_t bBase = aBase + 16384u;
    uint32_t dstA[4], dstB[4];
    const __half* srcA[4];
    const __half* srcB[4];
    #pragma unroll
    for (int it = 0; it < 4; it++) {
        const int i = it * 256 + tid;
        const int rr = i >> 3, cc = i & 7;
        const uint32_t sw = (uint32_t)(rr * 128 + ((cc ^ (rr & 7)) << 4));
        dstA[it] = aBase + sw;
        dstB[it] = bBase + sw;
        srcA[it] = Ag + (size_t)rr * DP2 + cc * 8;
        srcB[it] = Bg + (size_t)rr * DP2 + cc * 8;
    }

    uint32_t preA[4]; int a7[4];
    #pragma unroll
    for (int mf = 0; mf < 4; mf++) {
        const int rA = warp_m * 64 + mf * 16 + (lane & 7) + ((lane >> 3) & 1) * 8;
        preA[mf] = aBase + rA * 128;
        a7[mf] = rA & 7;
    }
    const int cA = lane >> 4;
    uint32_t preB[2]; int b7[2];
    #pragma unroll
    for (int g = 0; g < 2; g++) {
        const int rB = warp_n * 32 + g * 16 + (lane & 7) + (lane >> 4) * 8;
        preB[g] = bBase + rB * 128;
        b7[g] = rB & 7;
    }
    const int cB = (lane >> 3) & 1;

    uint32_t acc[4][4][2];
    #pragma unroll
    for (int mf = 0; mf < 4; mf++)
        #pragma unroll
        for (int nf = 0; nf < 4; nf++) {
            acc[mf][nf][0] = 0u;
            acc[mf][nf][1] = 0u;
        }

    #pragma unroll
    for (int it = 0; it < 4; it++) {
        CP_ASYNC16(dstA[it], srcA[it]);
        CP_ASYNC16(dstB[it], srcB[it]);
    }
    CP_COMMIT();
    #pragma unroll
    for (int it = 0; it < 4; it++) {
        CP_ASYNC16(dstA[it] + 32768u, srcA[it] + 64);
        CP_ASYNC16(dstB[it] + 32768u, srcB[it] + 64);
    }
    CP_COMMIT();

    int stage = 0;
    for (int ch = 0; ch < NCHUNK; ch++) {
        CP_WAIT1();
        __syncthreads();

        if (ch + 2 < NCHUNK) {
            const int nst = (stage + 2 >= 3) ? stage - 1 : stage + 2;
            const uint32_t so = (uint32_t)nst * 32768u;
            const int kc = (ch + 2) * 64;
            #pragma unroll
            for (int it = 0; it < 4; it++) {
                CP_ASYNC16(dstA[it] + so, srcA[it] + kc);
                CP_ASYNC16(dstB[it] + so, srcB[it] + kc);
            }
        }
        CP_COMMIT();

        const uint32_t stOff = (uint32_t)stage * 32768u;
        #pragma unroll
        for (int s = 0; s < 4; s++) {
            uint32_t af[4][4];
            #pragma unroll
            for (int mf = 0; mf < 4; mf++) {
                const uint32_t addr = preA[mf] + stOff + ((uint32_t)(((2 * s + cA) ^ a7[mf]) << 4));
                asm volatile("ldmatrix.sync.aligned.m8n8.x4.shared.b16 {%0,%1,%2,%3}, [%4];"
                    : "=r"(af[mf][0]), "=r"(af[mf][1]), "=r"(af[mf][2]), "=r"(af[mf][3])
                    : "r"(addr));
            }
            uint32_t bf[2][4];
            #pragma unroll
            for (int g = 0; g < 2; g++) {
                const uint32_t addr = preB[g] + stOff + ((uint32_t)(((2 * s + cB) ^ b7[g]) << 4));
                asm volatile("ldmatrix.sync.aligned.m8n8.x4.shared.b16 {%0,%1,%2,%3}, [%4];"
                    : "=r"(bf[g][0]), "=r"(bf[g][1]), "=r"(bf[g][2]), "=r"(bf[g][3])
                    : "r"(addr));
            }
            #pragma unroll
            for (int mf = 0; mf < 4; mf++)
                #pragma unroll
                for (int nf = 0; nf < 4; nf++) {
                    const uint32_t b0 = bf[nf >> 1][(nf & 1) * 2 + 0];
                    const uint32_t b1 = bf[nf >> 1][(nf & 1) * 2 + 1];
                    asm volatile(
                        "mma.sync.aligned.m16n8k16.row.col.f16.f16.f16.f16 "
                        "{%0,%1}, {%2,%3,%4,%5}, {%6,%7}, {%0,%1};"
                        : "+r"(acc[mf][nf][0]), "+r"(acc[mf][nf][1])
                        : "r"(af[mf][0]), "r"(af[mf][1]), "r"(af[mf][2]), "r"(af[mf][3]),
                          "r"(b0), "r"(b1));
                }
        }

        stage = (stage + 1 >= 3) ? 0 : stage + 1;
    }

    const int cluster = bcol * 4 + warp_n;
    #pragma unroll
    for (int mf = 0; mf < 4; mf++) {
        float mlo = -3.402823466e38f, mhi = -3.402823466e38f;
        #pragma unroll
        for (int nf = 0; nf < 4; nf++) {
            const float2 lo = __half22float2(*(const __half2*)&acc[mf][nf][0]);
            const float2 hi = __half22float2(*(const __half2*)&acc[mf][nf][1]);
            mlo = fmaxf(mlo, fmaxf(lo.x, lo.y));
            mhi = fmaxf(mhi, fmaxf(hi.x, hi.y));
        }
        mlo = fmaxf(mlo, __shfl_xor_sync(0xffffffffu, mlo, 1));
        mlo = fmaxf(mlo, __shfl_xor_sync(0xffffffffu, mlo, 2));
        mhi = fmaxf(mhi, __shfl_xor_sync(0xffffffffu, mhi, 1));
        mhi = fmaxf(mhi, __shfl_xor_sync(0xffffffffu, mhi, 2));
        if ((lane & 3) == 0) {
            const int grow = brow * 128 + warp_m * 64 + mf * 16 + (lane >> 2);
            g_pmax[z][grow * C_ + cluster] = mlo;
            g_pmax[z][(grow + 8) * C_ + cluster] = mhi;
        }
    }
}

// ---------------- Stage C: warp-per-sentence loss + fused reduction ----------
__global__ void __launch_bounds__(256) loss_kernel(float* __restrict__ out)
{
    const int tid = threadIdx.x;
    const int lane = tid & 31, w = tid >> 5;
    const int b = blockIdx.x * 8 + w;

    const float t0 = g_pmax[0][b * C_ + lane];
    const float t1 = g_pmax[0][b * C_ + 32 + lane];
    const float s0 = g_pmax[1][b * C_ + lane];
    const float s1 = g_pmax[1][b * C_ + 32 + lane];

    float m = fmaxf(t0, t1);
    #pragma unroll
    for (int o = 16; o > 0; o >>= 1)
        m = fmaxf(m, __shfl_xor_sync(0xffffffffu, m, o));

    const float e0 = expf(t0 - m);
    const float e1 = expf(t1 - m);
    float Z = e0 + e1;
    #pragma unroll
    for (int o = 16; o > 0; o >>= 1)
        Z += __shfl_xor_sync(0xffffffffu, Z, o);

    const float inv_Z = 1.f / Z;
    const float reli = inv_Z - (1.f / (float)C_);   // max prob = exp(0)/Z
    const float wgt = 1.f + 0.5f * fabsf(reli);
    const float d0 = e0 * inv_Z - s0;
    const float d1 = e1 * inv_Z - s1;
    float q = d0 * d0 + d1 * d1;
    #pragma unroll
    for (int o = 16; o > 0; o >>= 1)
        q += __shfl_xor_sync(0xffffffffu, q, o);
    if (lane == 0) g_lossb[b] = wgt * q;

    __shared__ int is_last;
    __shared__ float sh[8];
    __threadfence();
    __syncthreads();
    if (tid == 0) {
        const unsigned int o = atomicAdd(&g_cnt, 1u);
        is_last = (o == (unsigned int)(LOSS_BLOCKS - 1));
    }
    __syncthreads();
    if (is_last) {
        __threadfence();
        float sum = 0.f;
        for (int i = tid; i < B_; i += 256) sum += g_lossb[i];
        #pragma unroll
        for (int o = 16; o > 0; o >>= 1)
            sum += __shfl_xor_sync(0xffffffffu, sum, o);
        if (lane == 0) sh[w] = sum;
        __syncthreads();
        if (tid == 0) {
            float tot = 0.f;
            #pragma unroll
            for (int i = 0; i < 8; i++) tot += sh[i];
            out[0] = tot * (1.f / (float)B_);
            g_cnt = 0;   // reset for next graph replay
        }
    }
}

extern "C" void kernel_launch(void* const* d_in, const int* in_sizes, int n_in,
                              void* d_out, int out_size)
{
    const int* sents = nullptr;
    const int* seeds = nullptr;
    const float* mask = nullptr;
    const float* embT = nullptr;
    const float* embS = nullptr;
    int c131 = 0, c15m = 0;
    for (int i = 0; i < n_in; i++) {
        const int sz = in_sizes[i];
        if (sz == B_ * L_) {
            if (c131 == 0) sents = (const int*)d_in[i];
            else           mask  = (const float*)d_in[i];
            c131++;
        } else if (sz == S_ * LS_) {
            seeds = (const int*)d_in[i];
        } else if (sz == 50000 * D_) {
            if (c15m == 0) embT = (const float*)d_in[i];
            else           embS = (const float*)d_in[i];
            c15m++;
        }
    }

    cudaFuncSetAttribute(gemm_max_kernel,
                         cudaFuncAttributeMaxDynamicSharedMemorySize, GEMM_SMEM);

    emb_kernel<<<B_ + S_, 160>>>(sents, seeds, mask, embT, embS);
    gemm_max_kernel<<<dim3(16, 16, 2), 256, GEMM_SMEM>>>();
    loss_kernel<<<LOSS_BLOCKS, 256>>>((float*)d_out);
}